// round 11
// baseline (speedup 1.0000x reference)
#include <cuda_runtime.h>
#include <cuda_bf16.h>
#include <cstdint>

// ---------------------------------------------------------------------------
// GCN VGAE encoder (fp32, f32x2 FFMA 64x128-tile GEMMs, CSR gather 1 warp/node)
//   GEMM:   hs = X@W (raw)
//   gather: agg[v] = dinv[v]*hs[v] + sum_in dinv[s]*hs[s]
//   stage (fused in consumer GEMM): x = relu(dinv[v]*agg[v] + b)
// Pipelining (two streams, event-chained, race-free):
//   - CSR build (s2) overlaps gemm1 (main)
//   - gather1(hs1)->gemm2(writes hs2) and gather2(hs2)->gemm3(writes out) are
//     chunked into 4 row-ranges; separate hs buffers per layer eliminate the
//     WAR hazard between pipelined gemm writes and in-flight gather reads.
// ---------------------------------------------------------------------------

#define MAXN 50000
#define MAXE 800000
#define FDIM 128
#define CHUNKS 4

__device__ float g_dinv[MAXN];
__device__ int   g_degi[MAXN];
__device__ int   g_off [MAXN + 1];
__device__ int   g_cur [MAXN];
__device__ int   g_csr [MAXE];
__device__ int   g_bsum[256];
__device__ float g_hs1 [MAXN * FDIM];
__device__ float g_hs2 [MAXN * FDIM];
__device__ float g_aggA[MAXN * FDIM];
__device__ float g_aggB[MAXN * FDIM];

typedef unsigned long long ull;

#define SPLAT2(d, x) asm("mov.b64 %0, {%1, %1};" : "=l"(d) : "f"(x))
#define FMA2(d, a, b, c) \
    asm("fma.rn.f32x2 %0, %1, %2, %3;" : "=l"(d) : "l"(a), "l"(b), "l"(c))
#define UNPACK2(lo, hi, v) \
    asm("mov.b64 {%0, %1}, %2;" : "=f"(lo), "=f"(hi) : "l"(v))

// ======================= degree + CSR build =======================

__global__ void count_deg_kernel(const int* __restrict__ ei, int E) {
    int e = blockIdx.x * blockDim.x + threadIdx.x;
    if (e < E) atomicAdd(&g_degi[ei[E + e]], 1);
}

__global__ void scan1_kernel(int N) {
    __shared__ int s[256];
    int t = threadIdx.x;
    int i = blockIdx.x * 256 + t;
    s[t] = (i < N) ? g_degi[i] : 0;
    __syncthreads();
#pragma unroll
    for (int d = 128; d > 0; d >>= 1) {
        if (t < d) s[t] += s[t + d];
        __syncthreads();
    }
    if (t == 0) g_bsum[blockIdx.x] = s[0];
}

__global__ void scan3_kernel(int N, int nb) {
    __shared__ int bs[256];
    __shared__ int s[256];
    int t = threadIdx.x;

    int bv = (t < nb) ? g_bsum[t] : 0;
    bs[t] = bv;
    __syncthreads();
#pragma unroll
    for (int d = 1; d < 256; d <<= 1) {
        int v = (t >= d) ? bs[t - d] : 0;
        __syncthreads();
        bs[t] += v;
        __syncthreads();
    }
    int base = bs[blockIdx.x] - ((blockIdx.x < nb) ? g_bsum[blockIdx.x] : 0);

    int i = blockIdx.x * 256 + t;
    int deg = (i < N) ? g_degi[i] : 0;
    s[t] = deg;
    __syncthreads();
#pragma unroll
    for (int d = 1; d < 256; d <<= 1) {
        int v = (t >= d) ? s[t - d] : 0;
        __syncthreads();
        s[t] += v;
        __syncthreads();
    }
    if (i < N) {
        int off = base + s[t] - deg;
        g_off[i] = off;
        g_cur[i] = off;
        g_dinv[i] = rsqrtf((float)deg + 1.0f);
        if (i == N - 1) g_off[N] = off + deg;
    }
}

__global__ void fill_csr_kernel(const int* __restrict__ ei, int E) {
    int e = blockIdx.x * blockDim.x + threadIdx.x;
    if (e < E) {
        int d = ei[E + e];
        int pos = atomicAdd(&g_cur[d], 1);
        g_csr[pos] = ei[e];
    }
}

// ======================= GEMM machinery =======================
// 256 threads, tile 64 rows x 128 cols. Ws[128][128] + Xs[64][128] = 96KB smem.

#define GEMM_SMEM ((128 * 128 + 64 * 128) * 4)

__device__ __forceinline__ void load_xtile(float* Xs, const float* __restrict__ src,
                                           const float* __restrict__ bias, int fuse,
                                           int rowBase, int N, int t) {
#pragma unroll
    for (int i = 0; i < 8; i++) {
        int idx = t + i * 256;
        int r = idx >> 5, c4 = idx & 31;
        int rg = rowBase + r;
        float4 v = make_float4(0.f, 0.f, 0.f, 0.f);
        if (rg < N) {
            v = ((const float4*)src)[(size_t)rg * 32 + c4];
            if (fuse) {
                float dv = g_dinv[rg];
                float4 bb = ((const float4*)bias)[c4];
                v.x = fmaxf(v.x * dv + bb.x, 0.f);
                v.y = fmaxf(v.y * dv + bb.y, 0.f);
                v.z = fmaxf(v.z * dv + bb.z, 0.f);
                v.w = fmaxf(v.w * dv + bb.w, 0.f);
            }
        }
        ((float4*)Xs)[idx] = v;
    }
}

__device__ __forceinline__ void mm_tile(const float* Ws, const float* Xs,
                                        int c0, int r0, ull acc[8][2]) {
#pragma unroll
    for (int i = 0; i < 8; i++) { acc[i][0] = 0ull; acc[i][1] = 0ull; }

#pragma unroll 2
    for (int k0 = 0; k0 < 128; k0 += 4) {
        float4 a[8];
#pragma unroll
        for (int i = 0; i < 8; i++)
            a[i] = *(const float4*)(Xs + (r0 + i) * 128 + k0);
#pragma unroll
        for (int kk = 0; kk < 4; kk++) {
            ulonglong2 w = *(const ulonglong2*)(Ws + (k0 + kk) * 128 + c0);
#pragma unroll
            for (int i = 0; i < 8; i++) {
                ull s;
                SPLAT2(s, ((const float*)&a[i])[kk]);
                FMA2(acc[i][0], s, w.x, acc[i][0]);
                FMA2(acc[i][1], s, w.y, acc[i][1]);
            }
        }
    }
}

// conv GEMM over rows [rowStart, ...): hs_out = X@W (raw).
// stage0: X=xin, out=g_hs1 ; stage1: X=relu(dinv*aggA+bias), out=g_hs2
__global__ void __launch_bounds__(256)
gemm_conv_kernel(const float* __restrict__ xin,
                 const float* __restrict__ W,
                 const float* __restrict__ bias,
                 int N, int stage, int rowStart) {
    extern __shared__ float sm[];
    float* Ws = sm;
    float* Xs = sm + 128 * 128;
    const int t = threadIdx.x;
    const float* src = (stage == 0) ? xin : (const float*)g_aggA;
    float* hsout = (stage == 0) ? g_hs1 : g_hs2;

#pragma unroll
    for (int i = 0; i < 16; i++) {
        int idx = t + i * 256;
        ((float4*)Ws)[idx] = ((const float4*)W)[idx];
    }
    const int rowBase = rowStart + blockIdx.x * 64;
    load_xtile(Xs, src, bias, stage != 0, rowBase, N, t);
    __syncthreads();

    const int tx = t & 31, ty = t >> 5;
    const int c0 = tx * 4, r0 = ty * 8;
    ull acc[8][2];
    mm_tile(Ws, Xs, c0, r0, acc);

#pragma unroll
    for (int i = 0; i < 8; i++) {
        int r = rowBase + r0 + i;
        if (r < N) {
            float a0, a1, a2, a3;
            UNPACK2(a0, a1, acc[i][0]);
            UNPACK2(a2, a3, acc[i][1]);
            *(float4*)(hsout + (size_t)r * 128 + c0) = make_float4(a0, a1, a2, a3);
        }
    }
}

// final GEMM over rows [rowStart, ...): [mu|lv] = relu(dinv*aggB+b2)@[Wmu|Wlv]+bias
__global__ void __launch_bounds__(256)
gemm_final_kernel(const float* __restrict__ Wmu,
                  const float* __restrict__ Wlv,
                  const float* __restrict__ bmu,
                  const float* __restrict__ blv,
                  const float* __restrict__ b2,
                  float* __restrict__ out,
                  int N, int rowStart) {
    extern __shared__ float sm[];
    float* Ws = sm;
    float* Xs = sm + 128 * 128;
    const int t = threadIdx.x;

#pragma unroll
    for (int i = 0; i < 16; i++) {
        int idx = t + i * 256;
        int k = idx >> 5;
        int cc4 = idx & 31;
        float4 v = (cc4 < 16) ? ((const float4*)Wmu)[k * 16 + cc4]
                              : ((const float4*)Wlv)[k * 16 + (cc4 - 16)];
        ((float4*)Ws)[idx] = v;
    }
    const int rowBase = rowStart + blockIdx.x * 64;
    load_xtile(Xs, (const float*)g_aggB, b2, 1, rowBase, N, t);
    __syncthreads();

    const int tx = t & 31, ty = t >> 5;
    const int c0 = tx * 4, r0 = ty * 8;
    ull acc[8][2];
    mm_tile(Ws, Xs, c0, r0, acc);

    const bool is_mu = (c0 < 64);
    const int cl = is_mu ? c0 : (c0 - 64);
    float4 bs = is_mu ? *(const float4*)(bmu + cl) : *(const float4*)(blv + cl);
#pragma unroll
    for (int i = 0; i < 8; i++) {
        int r = rowBase + r0 + i;
        if (r < N) {
            float a0, a1, a2, a3;
            UNPACK2(a0, a1, acc[i][0]);
            UNPACK2(a2, a3, acc[i][1]);
            float* base = is_mu ? (out + (size_t)r * 64 + cl)
                                : (out + (size_t)N * 64 + (size_t)r * 64 + cl);
            *(float4*)base = make_float4(a0 + bs.x, a1 + bs.y, a2 + bs.z, a3 + bs.w);
        }
    }
}

// ==== gather over nodes [start, start+cnt):
//      agg[v] = dinv[v]*hs[v] + sum_in dinv[s]*hs[s] (1 warp/node) ===========
// which==0: hs=g_hs1, agg=g_aggA ; which==1: hs=g_hs2, agg=g_aggB

__global__ void gather_kernel(int start, int cnt, int N, int which) {
    int node = start + ((blockIdx.x * blockDim.x + threadIdx.x) >> 5);
    int lane = threadIdx.x & 31;
    if (node >= start + cnt || node >= N) return;
    const float* hs = which ? g_hs2 : g_hs1;
    float* agg = which ? g_aggB : g_aggA;

    const float4* hs4 = (const float4*)hs;
    float dv = g_dinv[node];
    float4 a = hs4[(size_t)node * 32 + lane];
    float4 acc = make_float4(a.x * dv, a.y * dv, a.z * dv, a.w * dv);

    int j = g_off[node];
    int end = g_off[node + 1];
    for (; j + 4 <= end; j += 4) {
        int s0 = g_csr[j], s1 = g_csr[j + 1], s2 = g_csr[j + 2], s3 = g_csr[j + 3];
        float d0 = g_dinv[s0], d1 = g_dinv[s1], d2 = g_dinv[s2], d3 = g_dinv[s3];
        float4 v0 = hs4[(size_t)s0 * 32 + lane];
        float4 v1 = hs4[(size_t)s1 * 32 + lane];
        float4 v2 = hs4[(size_t)s2 * 32 + lane];
        float4 v3 = hs4[(size_t)s3 * 32 + lane];
        acc.x += d0 * v0.x + d1 * v1.x + d2 * v2.x + d3 * v3.x;
        acc.y += d0 * v0.y + d1 * v1.y + d2 * v2.y + d3 * v3.y;
        acc.z += d0 * v0.z + d1 * v1.z + d2 * v2.z + d3 * v3.z;
        acc.w += d0 * v0.w + d1 * v1.w + d2 * v2.w + d3 * v3.w;
    }
    for (; j < end; j++) {
        int s = g_csr[j];
        float d = g_dinv[s];
        float4 v = hs4[(size_t)s * 32 + lane];
        acc.x += d * v.x; acc.y += d * v.y; acc.z += d * v.z; acc.w += d * v.w;
    }
    ((float4*)agg)[(size_t)node * 32 + lane] = acc;
}

// ======================= launch =======================

extern "C" void kernel_launch(void* const* d_in, const int* in_sizes, int n_in,
                              void* d_out, int out_size) {
    const float* x   = (const float*)d_in[0];
    const int*   ei  = (const int*)d_in[1];      // int32 edge_index [2, E]
    const float* W1  = (const float*)d_in[2];
    const float* b1  = (const float*)d_in[3];
    const float* W2  = (const float*)d_in[4];
    const float* b2  = (const float*)d_in[5];
    const float* Wmu = (const float*)d_in[6];
    const float* bmu = (const float*)d_in[7];
    const float* Wlv = (const float*)d_in[8];
    const float* blv = (const float*)d_in[9];
    float* out = (float*)d_out;

    const int N = in_sizes[0] / 128;
    const int E = in_sizes[1] / 2;

    cudaFuncSetAttribute(gemm_conv_kernel,
                         cudaFuncAttributeMaxDynamicSharedMemorySize, GEMM_SMEM);
    cudaFuncSetAttribute(gemm_final_kernel,
                         cudaFuncAttributeMaxDynamicSharedMemorySize, GEMM_SMEM);

    const int nb = (N + 255) / 256;
    const int gemm_blocks_full = (N + 63) / 64;

    int cstart[CHUNKS], ccnt[CHUNKS];
    {
        int cs = (N + CHUNKS - 1) / CHUNKS;
        for (int c = 0; c < CHUNKS; c++) {
            cstart[c] = c * cs;
            int e = cstart[c] + cs; if (e > N) e = N;
            ccnt[c] = (e > cstart[c]) ? (e - cstart[c]) : 0;
        }
    }

    void* degi_ptr = nullptr;
    cudaGetSymbolAddress(&degi_ptr, g_degi);

    cudaStream_t s2;
    cudaEvent_t evFork, evG1, evG2;
    cudaEvent_t ev1[CHUNKS], ev2[CHUNKS];
    cudaStreamCreateWithFlags(&s2, cudaStreamNonBlocking);
    cudaEventCreateWithFlags(&evFork, cudaEventDisableTiming);
    cudaEventCreateWithFlags(&evG1, cudaEventDisableTiming);
    cudaEventCreateWithFlags(&evG2, cudaEventDisableTiming);
    for (int c = 0; c < CHUNKS; c++) {
        cudaEventCreateWithFlags(&ev1[c], cudaEventDisableTiming);
        cudaEventCreateWithFlags(&ev2[c], cudaEventDisableTiming);
    }

    cudaEventRecord(evFork, 0);
    cudaStreamWaitEvent(s2, evFork, 0);

    // --- s2: degree + CSR (overlaps gemm1) ---
    cudaMemsetAsync(degi_ptr, 0, (size_t)N * sizeof(int), s2);
    count_deg_kernel<<<(E + 255) / 256, 256, 0, s2>>>(ei, E);
    scan1_kernel<<<nb, 256, 0, s2>>>(N);
    scan3_kernel<<<nb, 256, 0, s2>>>(N, nb);
    fill_csr_kernel<<<(E + 255) / 256, 256, 0, s2>>>(ei, E);

    // --- main: gemm1 -> hs1 (all rows) ---
    gemm_conv_kernel<<<gemm_blocks_full, 256, GEMM_SMEM>>>(x, W1, b1, N, 0, 0);
    cudaEventRecord(evG1, 0);

    // --- s2: gather1 chunks (hs1 -> aggA); needs CSR (in-order) + hs1 ---
    cudaStreamWaitEvent(s2, evG1, 0);
    for (int c = 0; c < CHUNKS; c++) {
        int gb = (ccnt[c] + 7) / 8;
        if (gb > 0)
            gather_kernel<<<gb, 256, 0, s2>>>(cstart[c], ccnt[c], N, 0);
        cudaEventRecord(ev1[c], s2);
    }

    // --- main: gemm2 chunks (aggA -> hs2); writes hs2, never hs1 ---
    for (int c = 0; c < CHUNKS; c++) {
        cudaStreamWaitEvent(0, ev1[c], 0);
        int gb = (ccnt[c] + 63) / 64;
        if (gb > 0)
            gemm_conv_kernel<<<gb, 256, GEMM_SMEM>>>(x, W2, b1, N, 1, cstart[c]);
    }
    cudaEventRecord(evG2, 0);

    // --- s2: gather2 chunks (hs2 -> aggB); needs all hs2 ---
    cudaStreamWaitEvent(s2, evG2, 0);
    for (int c = 0; c < CHUNKS; c++) {
        int gb = (ccnt[c] + 7) / 8;
        if (gb > 0)
            gather_kernel<<<gb, 256, 0, s2>>>(cstart[c], ccnt[c], N, 1);
        cudaEventRecord(ev2[c], s2);
    }

    // --- main: gemm3 chunks (aggB -> out); writes only out ---
    for (int c = 0; c < CHUNKS; c++) {
        cudaStreamWaitEvent(0, ev2[c], 0);
        int gb = (ccnt[c] + 63) / 64;
        if (gb > 0)
            gemm_final_kernel<<<gb, 256, GEMM_SMEM>>>(Wmu, Wlv, bmu, blv, b2, out,
                                                      N, cstart[c]);
    }

    cudaEventDestroy(evFork);
    cudaEventDestroy(evG1);
    cudaEventDestroy(evG2);
    for (int c = 0; c < CHUNKS; c++) {
        cudaEventDestroy(ev1[c]);
        cudaEventDestroy(ev2[c]);
    }
    cudaStreamDestroy(s2);
}

// round 12
// speedup vs baseline: 1.1802x; 1.1802x over previous
#include <cuda_runtime.h>
#include <cuda_fp16.h>
#include <cstdint>

// ---------------------------------------------------------------------------
// GCN VGAE encoder (f32x2 FFMA 64x128-tile GEMMs; CSR gather 1 warp/node).
//   GEMM:   hs = X@W (raw), stored FP16 (accumulation fp32; only storage is 16-bit)
//   gather: agg[v] = dinv[v]*hs[v] + sum_in dinv[s]*hs[s]   (fp32 accumulate)
//   stage (fused in consumer GEMM): x = relu(dinv[v]*agg[v] + b)
// CSR build (stream s2) overlaps gemm1 (main stream); fill_csr unrolled x4 to
// pipeline the ATOMG-with-return latency.
// ---------------------------------------------------------------------------

#define MAXN 50000
#define MAXE 800000
#define FDIM 128

__device__ float  g_dinv[MAXN];
__device__ int    g_degi[MAXN];
__device__ int    g_off [MAXN + 1];
__device__ int    g_cur [MAXN];
__device__ int    g_csr [MAXE];
__device__ int    g_bsum[256];
__device__ __half g_hs1 [MAXN * FDIM];
__device__ __half g_hs2 [MAXN * FDIM];
__device__ float  g_aggA[MAXN * FDIM];
__device__ float  g_aggB[MAXN * FDIM];

typedef unsigned long long ull;

#define SPLAT2(d, x) asm("mov.b64 %0, {%1, %1};" : "=l"(d) : "f"(x))
#define FMA2(d, a, b, c) \
    asm("fma.rn.f32x2 %0, %1, %2, %3;" : "=l"(d) : "l"(a), "l"(b), "l"(c))
#define UNPACK2(lo, hi, v) \
    asm("mov.b64 {%0, %1}, %2;" : "=f"(lo), "=f"(hi) : "l"(v))

__device__ __forceinline__ float4 h4_to_f4(uint2 r) {
    __half2 a = *(__half2*)&r.x;
    __half2 b = *(__half2*)&r.y;
    float2 fa = __half22float2(a);
    float2 fb = __half22float2(b);
    return make_float4(fa.x, fa.y, fb.x, fb.y);
}

// ======================= degree + CSR build =======================

__global__ void count_deg_kernel(const int* __restrict__ ei, int E) {
    int base = (blockIdx.x * blockDim.x + threadIdx.x) * 4;
#pragma unroll
    for (int u = 0; u < 4; u++) {
        int e = base + u;
        if (e < E) atomicAdd(&g_degi[ei[E + e]], 1);   // no return -> REDG
    }
}

__global__ void scan1_kernel(int N) {
    __shared__ int s[256];
    int t = threadIdx.x;
    int i = blockIdx.x * 256 + t;
    s[t] = (i < N) ? g_degi[i] : 0;
    __syncthreads();
#pragma unroll
    for (int d = 128; d > 0; d >>= 1) {
        if (t < d) s[t] += s[t + d];
        __syncthreads();
    }
    if (t == 0) g_bsum[blockIdx.x] = s[0];
}

__global__ void scan3_kernel(int N, int nb) {
    __shared__ int bs[256];
    __shared__ int s[256];
    int t = threadIdx.x;

    int bv = (t < nb) ? g_bsum[t] : 0;
    bs[t] = bv;
    __syncthreads();
#pragma unroll
    for (int d = 1; d < 256; d <<= 1) {
        int v = (t >= d) ? bs[t - d] : 0;
        __syncthreads();
        bs[t] += v;
        __syncthreads();
    }
    int base = bs[blockIdx.x] - ((blockIdx.x < nb) ? g_bsum[blockIdx.x] : 0);

    int i = blockIdx.x * 256 + t;
    int deg = (i < N) ? g_degi[i] : 0;
    s[t] = deg;
    __syncthreads();
#pragma unroll
    for (int d = 1; d < 256; d <<= 1) {
        int v = (t >= d) ? s[t - d] : 0;
        __syncthreads();
        s[t] += v;
        __syncthreads();
    }
    if (i < N) {
        int off = base + s[t] - deg;
        g_off[i] = off;
        g_cur[i] = off;
        g_dinv[i] = rsqrtf((float)deg + 1.0f);
        if (i == N - 1) g_off[N] = off + deg;
    }
}

// 4 edges/thread -> 4 in-flight ATOMG (318-cyc return latency pipelined)
__global__ void fill_csr_kernel(const int* __restrict__ ei, int E) {
    int base = (blockIdx.x * blockDim.x + threadIdx.x) * 4;
    int d[4], s[4], pos[4];
    bool p[4];
#pragma unroll
    for (int u = 0; u < 4; u++) {
        int e = base + u;
        p[u] = (e < E);
        if (p[u]) { d[u] = ei[E + e]; s[u] = ei[e]; }
    }
#pragma unroll
    for (int u = 0; u < 4; u++)
        if (p[u]) pos[u] = atomicAdd(&g_cur[d[u]], 1);
#pragma unroll
    for (int u = 0; u < 4; u++)
        if (p[u]) g_csr[pos[u]] = s[u];
}

// ======================= GEMM machinery =======================
// 256 threads, tile 64 rows x 128 cols. Ws[128][128] + Xs[64][128] = 96KB smem.

#define GEMM_SMEM ((128 * 128 + 64 * 128) * 4)

__device__ __forceinline__ void load_xtile(float* Xs, const float* __restrict__ src,
                                           const float* __restrict__ bias, int fuse,
                                           int rowBase, int N, int t) {
#pragma unroll
    for (int i = 0; i < 8; i++) {
        int idx = t + i * 256;
        int r = idx >> 5, c4 = idx & 31;
        int rg = rowBase + r;
        float4 v = make_float4(0.f, 0.f, 0.f, 0.f);
        if (rg < N) {
            v = ((const float4*)src)[(size_t)rg * 32 + c4];
            if (fuse) {
                float dv = g_dinv[rg];
                float4 bb = ((const float4*)bias)[c4];
                v.x = fmaxf(v.x * dv + bb.x, 0.f);
                v.y = fmaxf(v.y * dv + bb.y, 0.f);
                v.z = fmaxf(v.z * dv + bb.z, 0.f);
                v.w = fmaxf(v.w * dv + bb.w, 0.f);
            }
        }
        ((float4*)Xs)[idx] = v;
    }
}

__device__ __forceinline__ void mm_tile(const float* Ws, const float* Xs,
                                        int c0, int r0, ull acc[8][2]) {
#pragma unroll
    for (int i = 0; i < 8; i++) { acc[i][0] = 0ull; acc[i][1] = 0ull; }

#pragma unroll 2
    for (int k0 = 0; k0 < 128; k0 += 4) {
        float4 a[8];
#pragma unroll
        for (int i = 0; i < 8; i++)
            a[i] = *(const float4*)(Xs + (r0 + i) * 128 + k0);
#pragma unroll
        for (int kk = 0; kk < 4; kk++) {
            ulonglong2 w = *(const ulonglong2*)(Ws + (k0 + kk) * 128 + c0);
#pragma unroll
            for (int i = 0; i < 8; i++) {
                ull s;
                SPLAT2(s, ((const float*)&a[i])[kk]);
                FMA2(acc[i][0], s, w.x, acc[i][0]);
                FMA2(acc[i][1], s, w.y, acc[i][1]);
            }
        }
    }
}

// conv GEMM: hs_out(fp16) = X@W. stage0: X=xin -> hs1 ; stage1: X=relu(dinv*aggA+b) -> hs2
__global__ void __launch_bounds__(256)
gemm_conv_kernel(const float* __restrict__ xin,
                 const float* __restrict__ W,
                 const float* __restrict__ bias,
                 int N, int stage) {
    extern __shared__ float sm[];
    float* Ws = sm;
    float* Xs = sm + 128 * 128;
    const int t = threadIdx.x;
    const float* src = (stage == 0) ? xin : (const float*)g_aggA;
    __half* hsout = (stage == 0) ? g_hs1 : g_hs2;

#pragma unroll
    for (int i = 0; i < 16; i++) {
        int idx = t + i * 256;
        ((float4*)Ws)[idx] = ((const float4*)W)[idx];
    }
    const int rowBase = blockIdx.x * 64;
    load_xtile(Xs, src, bias, stage != 0, rowBase, N, t);
    __syncthreads();

    const int tx = t & 31, ty = t >> 5;
    const int c0 = tx * 4, r0 = ty * 8;
    ull acc[8][2];
    mm_tile(Ws, Xs, c0, r0, acc);

#pragma unroll
    for (int i = 0; i < 8; i++) {
        int r = rowBase + r0 + i;
        if (r < N) {
            float a0, a1, a2, a3;
            UNPACK2(a0, a1, acc[i][0]);
            UNPACK2(a2, a3, acc[i][1]);
            __half2 h0 = __floats2half2_rn(a0, a1);
            __half2 h1 = __floats2half2_rn(a2, a3);
            uint2 wv;
            wv.x = *(unsigned*)&h0;
            wv.y = *(unsigned*)&h1;
            *(uint2*)(hsout + (size_t)r * 128 + c0) = wv;
        }
    }
}

// final GEMM: [mu|lv] = relu(dinv*aggB+b2) @ [Wmu|Wlv] + bias (all fp32)
__global__ void __launch_bounds__(256)
gemm_final_kernel(const float* __restrict__ Wmu,
                  const float* __restrict__ Wlv,
                  const float* __restrict__ bmu,
                  const float* __restrict__ blv,
                  const float* __restrict__ b2,
                  float* __restrict__ out,
                  int N) {
    extern __shared__ float sm[];
    float* Ws = sm;
    float* Xs = sm + 128 * 128;
    const int t = threadIdx.x;

#pragma unroll
    for (int i = 0; i < 16; i++) {
        int idx = t + i * 256;
        int k = idx >> 5;
        int cc4 = idx & 31;
        float4 v = (cc4 < 16) ? ((const float4*)Wmu)[k * 16 + cc4]
                              : ((const float4*)Wlv)[k * 16 + (cc4 - 16)];
        ((float4*)Ws)[idx] = v;
    }
    const int rowBase = blockIdx.x * 64;
    load_xtile(Xs, (const float*)g_aggB, b2, 1, rowBase, N, t);
    __syncthreads();

    const int tx = t & 31, ty = t >> 5;
    const int c0 = tx * 4, r0 = ty * 8;
    ull acc[8][2];
    mm_tile(Ws, Xs, c0, r0, acc);

    const bool is_mu = (c0 < 64);
    const int cl = is_mu ? c0 : (c0 - 64);
    float4 bs = is_mu ? *(const float4*)(bmu + cl) : *(const float4*)(blv + cl);
#pragma unroll
    for (int i = 0; i < 8; i++) {
        int r = rowBase + r0 + i;
        if (r < N) {
            float a0, a1, a2, a3;
            UNPACK2(a0, a1, acc[i][0]);
            UNPACK2(a2, a3, acc[i][1]);
            float* base = is_mu ? (out + (size_t)r * 64 + cl)
                                : (out + (size_t)N * 64 + (size_t)r * 64 + cl);
            *(float4*)base = make_float4(a0 + bs.x, a1 + bs.y, a2 + bs.z, a3 + bs.w);
        }
    }
}

// ==== gather: agg[v] = dinv[v]*hs[v] + sum_in dinv[s]*hs[s] (1 warp/node) ===
// hs is fp16 (uint2 = 4 halfs per lane); accumulation fp32.

__global__ void gather_kernel(int N, int which) {
    int node = (blockIdx.x * blockDim.x + threadIdx.x) >> 5;
    int lane = threadIdx.x & 31;
    if (node >= N) return;
    const __half* hs = which ? g_hs2 : g_hs1;
    float* agg = which ? g_aggB : g_aggA;

    const uint2* hsv = (const uint2*)hs;   // 4 halfs (=4 cols) per lane
    float dv = g_dinv[node];
    float4 a = h4_to_f4(hsv[(size_t)node * 32 + lane]);
    float4 acc = make_float4(a.x * dv, a.y * dv, a.z * dv, a.w * dv);

    int j = g_off[node];
    int end = g_off[node + 1];
    for (; j + 4 <= end; j += 4) {
        int s0 = g_csr[j], s1 = g_csr[j + 1], s2 = g_csr[j + 2], s3 = g_csr[j + 3];
        float d0 = g_dinv[s0], d1 = g_dinv[s1], d2 = g_dinv[s2], d3 = g_dinv[s3];
        float4 v0 = h4_to_f4(hsv[(size_t)s0 * 32 + lane]);
        float4 v1 = h4_to_f4(hsv[(size_t)s1 * 32 + lane]);
        float4 v2 = h4_to_f4(hsv[(size_t)s2 * 32 + lane]);
        float4 v3 = h4_to_f4(hsv[(size_t)s3 * 32 + lane]);
        acc.x += d0 * v0.x + d1 * v1.x + d2 * v2.x + d3 * v3.x;
        acc.y += d0 * v0.y + d1 * v1.y + d2 * v2.y + d3 * v3.y;
        acc.z += d0 * v0.z + d1 * v1.z + d2 * v2.z + d3 * v3.z;
        acc.w += d0 * v0.w + d1 * v1.w + d2 * v2.w + d3 * v3.w;
    }
    for (; j < end; j++) {
        int s = g_csr[j];
        float d = g_dinv[s];
        float4 v = h4_to_f4(hsv[(size_t)s * 32 + lane]);
        acc.x += d * v.x; acc.y += d * v.y; acc.z += d * v.z; acc.w += d * v.w;
    }
    ((float4*)agg)[(size_t)node * 32 + lane] = acc;
}

// ======================= launch =======================

extern "C" void kernel_launch(void* const* d_in, const int* in_sizes, int n_in,
                              void* d_out, int out_size) {
    const float* x   = (const float*)d_in[0];
    const int*   ei  = (const int*)d_in[1];      // int32 edge_index [2, E]
    const float* W1  = (const float*)d_in[2];
    const float* b1  = (const float*)d_in[3];
    const float* W2  = (const float*)d_in[4];
    const float* b2  = (const float*)d_in[5];
    const float* Wmu = (const float*)d_in[6];
    const float* bmu = (const float*)d_in[7];
    const float* Wlv = (const float*)d_in[8];
    const float* blv = (const float*)d_in[9];
    float* out = (float*)d_out;

    const int N = in_sizes[0] / 128;
    const int E = in_sizes[1] / 2;

    cudaFuncSetAttribute(gemm_conv_kernel,
                         cudaFuncAttributeMaxDynamicSharedMemorySize, GEMM_SMEM);
    cudaFuncSetAttribute(gemm_final_kernel,
                         cudaFuncAttributeMaxDynamicSharedMemorySize, GEMM_SMEM);

    const int nb = (N + 255) / 256;
    const int gemm_blocks = (N + 63) / 64;
    const int gath_blocks = (N + 7) / 8;          // 1 warp/node, 8 warps/block
    const int e4_blocks = ((E + 3) / 4 + 255) / 256;

    void* degi_ptr = nullptr;
    cudaGetSymbolAddress(&degi_ptr, g_degi);

    cudaStream_t s2;
    cudaEvent_t evFork, evJoin;
    cudaStreamCreateWithFlags(&s2, cudaStreamNonBlocking);
    cudaEventCreateWithFlags(&evFork, cudaEventDisableTiming);
    cudaEventCreateWithFlags(&evJoin, cudaEventDisableTiming);

    cudaEventRecord(evFork, 0);
    cudaStreamWaitEvent(s2, evFork, 0);

    // --- s2: degree + CSR (overlaps gemm1) ---
    cudaMemsetAsync(degi_ptr, 0, (size_t)N * sizeof(int), s2);
    count_deg_kernel<<<e4_blocks, 256, 0, s2>>>(ei, E);
    scan1_kernel<<<nb, 256, 0, s2>>>(N);
    scan3_kernel<<<nb, 256, 0, s2>>>(N, nb);
    fill_csr_kernel<<<e4_blocks, 256, 0, s2>>>(ei, E);
    cudaEventRecord(evJoin, s2);

    // --- main: gemm1 -> hs1(fp16) ---
    gemm_conv_kernel<<<gemm_blocks, 256, GEMM_SMEM>>>(x, W1, b1, N, 0);

    cudaStreamWaitEvent(0, evJoin, 0);

    gather_kernel<<<gath_blocks, 256>>>(N, 0);                          // hs1 -> aggA
    gemm_conv_kernel<<<gemm_blocks, 256, GEMM_SMEM>>>(x, W2, b1, N, 1); // aggA -> hs2
    gather_kernel<<<gath_blocks, 256>>>(N, 1);                          // hs2 -> aggB
    gemm_final_kernel<<<gemm_blocks, 256, GEMM_SMEM>>>(Wmu, Wlv, bmu, blv, b2, out, N);

    cudaEventDestroy(evFork);
    cudaEventDestroy(evJoin);
    cudaStreamDestroy(s2);
}

// round 13
// speedup vs baseline: 1.5558x; 1.3183x over previous
#include <cuda_runtime.h>
#include <cuda_fp16.h>
#include <cstdint>

// ---------------------------------------------------------------------------
// GCN VGAE encoder — tf32 tensor-core GEMMs (mma.sync m16n8k8, fp32 accum),
// fp16 hs storage, CSR gather 1 warp/node, CSR build overlapped with gemm1.
//   GEMM:   hs = X@W (tf32 mma, fp16 store)
//   gather: agg[v] = dinv[v]*hs[v] + sum_in dinv[s]*hs[s]  (fp32)
//   stage (fused in consumer GEMM): x = relu(dinv[v]*agg[v] + b)
// ---------------------------------------------------------------------------

#define MAXN 50000
#define MAXE 800000
#define FDIM 128

__device__ float  g_dinv[MAXN];
__device__ int    g_degi[MAXN];
__device__ int    g_off [MAXN + 1];
__device__ int    g_cur [MAXN];
__device__ int    g_csr [MAXE];
__device__ int    g_bsum[256];
__device__ __half g_hs1 [MAXN * FDIM];
__device__ __half g_hs2 [MAXN * FDIM];
__device__ float  g_aggA[MAXN * FDIM];
__device__ float  g_aggB[MAXN * FDIM];

__device__ __forceinline__ unsigned f2tf32(float f) {
    unsigned u;
    asm("cvt.rna.tf32.f32 %0, %1;" : "=r"(u) : "f"(f));
    return u;
}

__device__ __forceinline__ void mma_tf32(float c[4],
                                         unsigned a0, unsigned a1,
                                         unsigned a2, unsigned a3,
                                         unsigned b0, unsigned b1) {
    asm volatile(
        "mma.sync.aligned.m16n8k8.row.col.f32.tf32.tf32.f32 "
        "{%0,%1,%2,%3}, {%4,%5,%6,%7}, {%8,%9}, {%0,%1,%2,%3};\n"
        : "+f"(c[0]), "+f"(c[1]), "+f"(c[2]), "+f"(c[3])
        : "r"(a0), "r"(a1), "r"(a2), "r"(a3), "r"(b0), "r"(b1));
}

__device__ __forceinline__ float4 h4_to_f4(uint2 r) {
    __half2 a = *(__half2*)&r.x;
    __half2 b = *(__half2*)&r.y;
    float2 fa = __half22float2(a);
    float2 fb = __half22float2(b);
    return make_float4(fa.x, fa.y, fb.x, fb.y);
}

// ======================= degree + CSR build =======================

__global__ void count_deg_kernel(const int* __restrict__ ei, int E) {
    int e = blockIdx.x * blockDim.x + threadIdx.x;
    if (e < E) atomicAdd(&g_degi[ei[E + e]], 1);
}

__global__ void scan1_kernel(int N) {
    __shared__ int s[256];
    int t = threadIdx.x;
    int i = blockIdx.x * 256 + t;
    s[t] = (i < N) ? g_degi[i] : 0;
    __syncthreads();
#pragma unroll
    for (int d = 128; d > 0; d >>= 1) {
        if (t < d) s[t] += s[t + d];
        __syncthreads();
    }
    if (t == 0) g_bsum[blockIdx.x] = s[0];
}

__global__ void scan3_kernel(int N, int nb) {
    __shared__ int bs[256];
    __shared__ int s[256];
    int t = threadIdx.x;

    int bv = (t < nb) ? g_bsum[t] : 0;
    bs[t] = bv;
    __syncthreads();
#pragma unroll
    for (int d = 1; d < 256; d <<= 1) {
        int v = (t >= d) ? bs[t - d] : 0;
        __syncthreads();
        bs[t] += v;
        __syncthreads();
    }
    int base = bs[blockIdx.x] - ((blockIdx.x < nb) ? g_bsum[blockIdx.x] : 0);

    int i = blockIdx.x * 256 + t;
    int deg = (i < N) ? g_degi[i] : 0;
    s[t] = deg;
    __syncthreads();
#pragma unroll
    for (int d = 1; d < 256; d <<= 1) {
        int v = (t >= d) ? s[t - d] : 0;
        __syncthreads();
        s[t] += v;
        __syncthreads();
    }
    if (i < N) {
        int off = base + s[t] - deg;
        g_off[i] = off;
        g_cur[i] = off;
        g_dinv[i] = rsqrtf((float)deg + 1.0f);
        if (i == N - 1) g_off[N] = off + deg;
    }
}

__global__ void fill_csr_kernel(const int* __restrict__ ei, int E) {
    int e = blockIdx.x * blockDim.x + threadIdx.x;
    if (e < E) {
        int d = ei[E + e];
        int pos = atomicAdd(&g_cur[d], 1);
        g_csr[pos] = ei[e];
    }
}

// ======================= tf32 GEMM machinery =======================
// Block: 64 rows x 128 cols, 256 threads (8 warps).
// Warp w: rows (w&3)*16..+15, cols (w>>2)*64..+63 -> 8 ntiles x 16 ksteps mma.
// SMEM: Wp = B-fragments [16 ks][16 nt][32 lanes] float2 (tf32 bits) = 64KB,
//       Xs = fp32 [64][132] (pad 4) = 33KB.   Total 99328B, 2 blocks/SM.

#define XS_STRIDE 132
#define WP_F2     (16 * 16 * 32)                 // float2 count
#define GEMM_SMEM (WP_F2 * 8 + 64 * XS_STRIDE * 4)

// Permute W[128][128] (k-major rows) into B-fragment order, tf32-rounded.
__device__ __forceinline__ void stage_w_conv(float2* Wp, const float* __restrict__ W, int t) {
#pragma unroll
    for (int i = t; i < WP_F2; i += 256) {
        int lane = i & 31, nt = (i >> 5) & 15, ks = i >> 9;
        int tt = lane & 3, g = lane >> 2;
        int k0 = ks * 8 + tt, n0 = nt * 8 + g;
        float b0 = W[k0 * 128 + n0];
        float b1 = W[(k0 + 4) * 128 + n0];
        float2 v;
        *(unsigned*)&v.x = f2tf32(b0);
        *(unsigned*)&v.y = f2tf32(b1);
        Wp[i] = v;
    }
}

// Same but W = [Wmu | Wlv], each [128][64] row-major.
__device__ __forceinline__ void stage_w_final(float2* Wp,
                                              const float* __restrict__ Wmu,
                                              const float* __restrict__ Wlv, int t) {
#pragma unroll
    for (int i = t; i < WP_F2; i += 256) {
        int lane = i & 31, nt = (i >> 5) & 15, ks = i >> 9;
        int tt = lane & 3, g = lane >> 2;
        int k0 = ks * 8 + tt, n0 = nt * 8 + g;
        const float* Wa = (n0 < 64) ? Wmu : Wlv;
        int nl = (n0 < 64) ? n0 : (n0 - 64);
        float b0 = Wa[k0 * 64 + nl];
        float b1 = Wa[(k0 + 4) * 64 + nl];
        float2 v;
        *(unsigned*)&v.x = f2tf32(b0);
        *(unsigned*)&v.y = f2tf32(b1);
        Wp[i] = v;
    }
}

// Stage X tile (64 rows x 128 cols fp32, padded rows); optional relu(dinv*v+b).
__device__ __forceinline__ void stage_x(float* Xs, const float* __restrict__ src,
                                        const float* __restrict__ bias, int fuse,
                                        int rowBase, int N, int t) {
#pragma unroll
    for (int i = 0; i < 8; i++) {
        int idx = t + i * 256;            // 0..2047 float4 slots
        int r = idx >> 5, c4 = idx & 31;
        int rg = rowBase + r;
        float4 v = make_float4(0.f, 0.f, 0.f, 0.f);
        if (rg < N) {
            v = ((const float4*)src)[(size_t)rg * 32 + c4];
            if (fuse) {
                float dv = g_dinv[rg];
                float4 bb = ((const float4*)bias)[c4];
                v.x = fmaxf(v.x * dv + bb.x, 0.f);
                v.y = fmaxf(v.y * dv + bb.y, 0.f);
                v.z = fmaxf(v.z * dv + bb.z, 0.f);
                v.w = fmaxf(v.w * dv + bb.w, 0.f);
            }
        }
        *(float4*)(Xs + r * XS_STRIDE + c4 * 4) = v;
    }
}

// Warp-level 16x64x128 mma: c[nt2][4] accumulators.
__device__ __forceinline__ void mma_warp(const float* Xs, const float2* Wp,
                                         int rg, int cg, int lane, float c[8][4]) {
    const int g = lane >> 2, t4 = lane & 3;
#pragma unroll
    for (int nt2 = 0; nt2 < 8; nt2++)
#pragma unroll
        for (int i = 0; i < 4; i++) c[nt2][i] = 0.f;

#pragma unroll
    for (int ks = 0; ks < 16; ks++) {
        const float* xb = Xs + (rg * 16 + g) * XS_STRIDE + ks * 8 + t4;
        unsigned a0 = f2tf32(xb[0]);
        unsigned a1 = f2tf32(xb[8 * XS_STRIDE]);
        unsigned a2 = f2tf32(xb[4]);
        unsigned a3 = f2tf32(xb[8 * XS_STRIDE + 4]);
        const float2* wrow = Wp + (ks * 16 + cg * 8) * 32 + lane;
#pragma unroll
        for (int nt2 = 0; nt2 < 8; nt2++) {
            float2 b = wrow[nt2 * 32];
            mma_tf32(c[nt2], a0, a1, a2, a3,
                     *(unsigned*)&b.x, *(unsigned*)&b.y);
        }
    }
}

// conv GEMM: hs_out(fp16) = X@W. stage0: X=xin -> hs1 ; stage1: relu(dinv*aggA+b) -> hs2
__global__ void __launch_bounds__(256)
gemm_conv_kernel(const float* __restrict__ xin,
                 const float* __restrict__ W,
                 const float* __restrict__ bias,
                 int N, int stage) {
    extern __shared__ float sm[];
    float2* Wp = (float2*)sm;
    float* Xs = sm + WP_F2 * 2;
    const int t = threadIdx.x;
    const float* src = (stage == 0) ? xin : (const float*)g_aggA;
    __half* hsout = (stage == 0) ? g_hs1 : g_hs2;

    stage_w_conv(Wp, W, t);
    const int rowBase = blockIdx.x * 64;
    stage_x(Xs, src, bias, stage != 0, rowBase, N, t);
    __syncthreads();

    const int lane = t & 31, w = t >> 5;
    const int rg = w & 3, cg = w >> 2;
    float c[8][4];
    mma_warp(Xs, Wp, rg, cg, lane, c);

    const int g = lane >> 2, t4 = lane & 3;
    const int r0 = rowBase + rg * 16 + g;
    const int r1 = r0 + 8;
#pragma unroll
    for (int nt2 = 0; nt2 < 8; nt2++) {
        int col = cg * 64 + nt2 * 8 + 2 * t4;
        if (r0 < N) {
            __half2 h = __floats2half2_rn(c[nt2][0], c[nt2][1]);
            *(unsigned*)(hsout + (size_t)r0 * 128 + col) = *(unsigned*)&h;
        }
        if (r1 < N) {
            __half2 h = __floats2half2_rn(c[nt2][2], c[nt2][3]);
            *(unsigned*)(hsout + (size_t)r1 * 128 + col) = *(unsigned*)&h;
        }
    }
}

// final GEMM: [mu|lv] = relu(dinv*aggB+b2) @ [Wmu|Wlv] + bias
__global__ void __launch_bounds__(256)
gemm_final_kernel(const float* __restrict__ Wmu,
                  const float* __restrict__ Wlv,
                  const float* __restrict__ bmu,
                  const float* __restrict__ blv,
                  const float* __restrict__ b2,
                  float* __restrict__ out,
                  int N) {
    extern __shared__ float sm[];
    float2* Wp = (float2*)sm;
    float* Xs = sm + WP_F2 * 2;
    const int t = threadIdx.x;

    stage_w_final(Wp, Wmu, Wlv, t);
    const int rowBase = blockIdx.x * 64;
    stage_x(Xs, (const float*)g_aggB, b2, 1, rowBase, N, t);
    __syncthreads();

    const int lane = t & 31, w = t >> 5;
    const int rg = w & 3, cg = w >> 2;
    float c[8][4];
    mma_warp(Xs, Wp, rg, cg, lane, c);

    const int g = lane >> 2, t4 = lane & 3;
    const int r0 = rowBase + rg * 16 + g;
    const int r1 = r0 + 8;
    const float* bsrc = cg ? blv : bmu;
    const size_t obase = cg ? (size_t)N * 64 : 0;
#pragma unroll
    for (int nt2 = 0; nt2 < 8; nt2++) {
        int colL = nt2 * 8 + 2 * t4;      // local col within mu or lv (0..63)
        float bx = bsrc[colL], by = bsrc[colL + 1];
        if (r0 < N) {
            float2 o = make_float2(c[nt2][0] + bx, c[nt2][1] + by);
            *(float2*)(out + obase + (size_t)r0 * 64 + colL) = o;
        }
        if (r1 < N) {
            float2 o = make_float2(c[nt2][2] + bx, c[nt2][3] + by);
            *(float2*)(out + obase + (size_t)r1 * 64 + colL) = o;
        }
    }
}

// ==== gather: agg[v] = dinv[v]*hs[v] + sum_in dinv[s]*hs[s] (1 warp/node) ===

__global__ void gather_kernel(int N, int which) {
    int node = (blockIdx.x * blockDim.x + threadIdx.x) >> 5;
    int lane = threadIdx.x & 31;
    if (node >= N) return;
    const __half* hs = which ? g_hs2 : g_hs1;
    float* agg = which ? g_aggB : g_aggA;

    const uint2* hsv = (const uint2*)hs;   // 4 halfs per lane
    float dv = g_dinv[node];
    float4 a = h4_to_f4(hsv[(size_t)node * 32 + lane]);
    float4 acc = make_float4(a.x * dv, a.y * dv, a.z * dv, a.w * dv);

    int j = g_off[node];
    int end = g_off[node + 1];
    for (; j + 4 <= end; j += 4) {
        int s0 = g_csr[j], s1 = g_csr[j + 1], s2 = g_csr[j + 2], s3 = g_csr[j + 3];
        float d0 = g_dinv[s0], d1 = g_dinv[s1], d2 = g_dinv[s2], d3 = g_dinv[s3];
        float4 v0 = h4_to_f4(hsv[(size_t)s0 * 32 + lane]);
        float4 v1 = h4_to_f4(hsv[(size_t)s1 * 32 + lane]);
        float4 v2 = h4_to_f4(hsv[(size_t)s2 * 32 + lane]);
        float4 v3 = h4_to_f4(hsv[(size_t)s3 * 32 + lane]);
        acc.x += d0 * v0.x + d1 * v1.x + d2 * v2.x + d3 * v3.x;
        acc.y += d0 * v0.y + d1 * v1.y + d2 * v2.y + d3 * v3.y;
        acc.z += d0 * v0.z + d1 * v1.z + d2 * v2.z + d3 * v3.z;
        acc.w += d0 * v0.w + d1 * v1.w + d2 * v2.w + d3 * v3.w;
    }
    for (; j < end; j++) {
        int s = g_csr[j];
        float d = g_dinv[s];
        float4 v = h4_to_f4(hsv[(size_t)s * 32 + lane]);
        acc.x += d * v.x; acc.y += d * v.y; acc.z += d * v.z; acc.w += d * v.w;
    }
    ((float4*)agg)[(size_t)node * 32 + lane] = acc;
}

// ======================= launch =======================

extern "C" void kernel_launch(void* const* d_in, const int* in_sizes, int n_in,
                              void* d_out, int out_size) {
    const float* x   = (const float*)d_in[0];
    const int*   ei  = (const int*)d_in[1];      // int32 edge_index [2, E]
    const float* W1  = (const float*)d_in[2];
    const float* b1  = (const float*)d_in[3];
    const float* W2  = (const float*)d_in[4];
    const float* b2  = (const float*)d_in[5];
    const float* Wmu = (const float*)d_in[6];
    const float* bmu = (const float*)d_in[7];
    const float* Wlv = (const float*)d_in[8];
    const float* blv = (const float*)d_in[9];
    float* out = (float*)d_out;

    const int N = in_sizes[0] / 128;
    const int E = in_sizes[1] / 2;

    cudaFuncSetAttribute(gemm_conv_kernel,
                         cudaFuncAttributeMaxDynamicSharedMemorySize, GEMM_SMEM);
    cudaFuncSetAttribute(gemm_final_kernel,
                         cudaFuncAttributeMaxDynamicSharedMemorySize, GEMM_SMEM);

    const int nb = (N + 255) / 256;
    const int gemm_blocks = (N + 63) / 64;
    const int gath_blocks = (N + 7) / 8;

    void* degi_ptr = nullptr;
    cudaGetSymbolAddress(&degi_ptr, g_degi);

    cudaStream_t s2;
    cudaEvent_t evFork, evJoin;
    cudaStreamCreateWithFlags(&s2, cudaStreamNonBlocking);
    cudaEventCreateWithFlags(&evFork, cudaEventDisableTiming);
    cudaEventCreateWithFlags(&evJoin, cudaEventDisableTiming);

    cudaEventRecord(evFork, 0);
    cudaStreamWaitEvent(s2, evFork, 0);

    // --- s2: degree + CSR (overlaps gemm1) ---
    cudaMemsetAsync(degi_ptr, 0, (size_t)N * sizeof(int), s2);
    count_deg_kernel<<<(E + 255) / 256, 256, 0, s2>>>(ei, E);
    scan1_kernel<<<nb, 256, 0, s2>>>(N);
    scan3_kernel<<<nb, 256, 0, s2>>>(N, nb);
    fill_csr_kernel<<<(E + 255) / 256, 256, 0, s2>>>(ei, E);
    cudaEventRecord(evJoin, s2);

    // --- main: gemm1 -> hs1(fp16) ---
    gemm_conv_kernel<<<gemm_blocks, 256, GEMM_SMEM>>>(x, W1, b1, N, 0);

    cudaStreamWaitEvent(0, evJoin, 0);

    gather_kernel<<<gath_blocks, 256>>>(N, 0);                          // hs1 -> aggA
    gemm_conv_kernel<<<gemm_blocks, 256, GEMM_SMEM>>>(x, W2, b1, N, 1); // aggA -> hs2
    gather_kernel<<<gath_blocks, 256>>>(N, 1);                          // hs2 -> aggB
    gemm_final_kernel<<<gemm_blocks, 256, GEMM_SMEM>>>(Wmu, Wlv, bmu, blv, b2, out, N);

    cudaEventDestroy(evFork);
    cudaEventDestroy(evJoin);
    cudaStreamDestroy(s2);
}